// round 1
// baseline (speedup 1.0000x reference)
#include <cuda_runtime.h>
#include <math.h>

#define MHA_B  2
#define MHA_S  2048
#define MHA_D  1024
#define MHA_H  16
#define MHA_HD 64
#define NTOK   (MHA_B * MHA_S)

// Scratch (allocation-free rule: __device__ globals)
__device__ float g_Q[NTOK * MHA_D];
__device__ float g_K[NTOK * MHA_D];
__device__ float g_V[NTOK * MHA_D];
__device__ float g_C[NTOK * MHA_D];

// ---------------------------------------------------------------------------
// SGEMM: C[M,N] = A[M,K] * B[K,N] (+ bias), all row-major.
// BM=BN=128, BK=8, 256 threads, 8x8 register microtile per thread.
// Assumes M%128==0, N%128==0, K%8==0 (true for all uses here).
// ---------------------------------------------------------------------------
template <bool BIAS>
__global__ __launch_bounds__(256, 2) void sgemm_kernel(
    const float* __restrict__ A, const float* __restrict__ B,
    const float* __restrict__ bias, float* __restrict__ C,
    int M, int N, int K)
{
    __shared__ float As[8][132];   // [k][m], padded to break store conflicts
    __shared__ float Bs[8][128];   // [k][n]

    const int tid = threadIdx.x;
    const int tx = tid & 15;       // 0..15 -> N microtile
    const int ty = tid >> 4;       // 0..15 -> M microtile
    const int m0 = blockIdx.y * 128;
    const int n0 = blockIdx.x * 128;

    // A-tile loader: 128 rows x 8 cols = 256 float4
    const int arow = tid >> 1;            // 0..127
    const int acol = (tid & 1) * 4;       // 0 or 4
    // B-tile loader: 8 rows x 128 cols = 256 float4
    const int brow = tid >> 5;            // 0..7
    const int bcol = (tid & 31) * 4;      // 0..124

    const float* Aptr = A + (size_t)(m0 + arow) * K + acol;
    const float* Bptr = B + (size_t)brow * N + n0 + bcol;

    float acc[8][8];
    #pragma unroll
    for (int i = 0; i < 8; i++)
        #pragma unroll
        for (int j = 0; j < 8; j++) acc[i][j] = 0.0f;

    for (int kt = 0; kt < K; kt += 8) {
        float4 av = *(const float4*)(Aptr + kt);
        float4 bv = *(const float4*)(Bptr + (size_t)kt * N);
        As[acol + 0][arow] = av.x;
        As[acol + 1][arow] = av.y;
        As[acol + 2][arow] = av.z;
        As[acol + 3][arow] = av.w;
        *(float4*)&Bs[brow][bcol] = bv;
        __syncthreads();

        #pragma unroll
        for (int k = 0; k < 8; k++) {
            float a[8], b[8];
            *(float4*)(a)     = *(const float4*)&As[k][ty * 8];
            *(float4*)(a + 4) = *(const float4*)&As[k][ty * 8 + 4];
            *(float4*)(b)     = *(const float4*)&Bs[k][tx * 8];
            *(float4*)(b + 4) = *(const float4*)&Bs[k][tx * 8 + 4];
            #pragma unroll
            for (int i = 0; i < 8; i++)
                #pragma unroll
                for (int j = 0; j < 8; j++)
                    acc[i][j] = fmaf(a[i], b[j], acc[i][j]);
        }
        __syncthreads();
    }

    // Epilogue
    float bvals[8];
    if (BIAS) {
        #pragma unroll
        for (int j = 0; j < 8; j++) bvals[j] = bias[n0 + tx * 8 + j];
    }
    #pragma unroll
    for (int i = 0; i < 8; i++) {
        const size_t row = (size_t)(m0 + ty * 8 + i) * N + n0 + tx * 8;
        float4 o0, o1;
        o0.x = acc[i][0]; o0.y = acc[i][1]; o0.z = acc[i][2]; o0.w = acc[i][3];
        o1.x = acc[i][4]; o1.y = acc[i][5]; o1.z = acc[i][6]; o1.w = acc[i][7];
        if (BIAS) {
            o0.x += bvals[0]; o0.y += bvals[1]; o0.z += bvals[2]; o0.w += bvals[3];
            o1.x += bvals[4]; o1.y += bvals[5]; o1.z += bvals[6]; o1.w += bvals[7];
        }
        *(float4*)&C[row]     = o0;
        *(float4*)&C[row + 4] = o1;
    }
}

// ---------------------------------------------------------------------------
// Flash attention, fp32, causal. One block = 64 queries of one (b,h).
// 256 threads; each thread owns a 4x4 microtile of the 64x64 score tile
// and a 4(rows)x4(hd-cols) slice of the output accumulator.
// Q/K/V buffers are [NTOK][1024] row-major; head h occupies cols h*64..h*64+63.
// Output written in [B,S,H,HD] layout (== [4096][1024] row-major) for Wo GEMM.
// ---------------------------------------------------------------------------
#define FA_AS 65   // smem row stride (64 + 1 pad)

__global__ __launch_bounds__(256) void flash_kernel(
    const float* __restrict__ Qg, const float* __restrict__ Kg,
    const float* __restrict__ Vg, float* __restrict__ Og)
{
    extern __shared__ float sm[];
    float* Qs = sm;
    float* Ks = sm + 64 * FA_AS;
    float* Vs = sm + 2 * 64 * FA_AS;
    float* Ps = sm + 3 * 64 * FA_AS;

    const int tid = threadIdx.x;
    const int tx = tid & 15;       // key / hd-col group
    const int ty = tid >> 4;       // query row group
    const int b  = blockIdx.y >> 4;
    const int h  = blockIdx.y & 15;
    const int q0 = blockIdx.x * 64;
    const size_t base = (size_t)b * MHA_S * MHA_D + (size_t)h * MHA_HD;

    // Load Q tile: 64 rows x 64 cols
    #pragma unroll
    for (int i = 0; i < 16; i++) {
        int idx = i * 256 + tid;
        int r = idx >> 6, c = idx & 63;
        Qs[r * FA_AS + c] = Qg[base + (size_t)(q0 + r) * MHA_D + c];
    }

    float m_i[4], l_i[4], o[4][4];
    #pragma unroll
    for (int i = 0; i < 4; i++) {
        m_i[i] = -1e30f;
        l_i[i] = 0.0f;
        #pragma unroll
        for (int j = 0; j < 4; j++) o[i][j] = 0.0f;
    }
    __syncthreads();

    const int ktmax = blockIdx.x;
    for (int kt = 0; kt <= ktmax; kt++) {
        const int k0 = kt * 64;
        // Load K and V tiles
        #pragma unroll
        for (int i = 0; i < 16; i++) {
            int idx = i * 256 + tid;
            int r = idx >> 6, c = idx & 63;
            Ks[r * FA_AS + c] = Kg[base + (size_t)(k0 + r) * MHA_D + c];
            Vs[r * FA_AS + c] = Vg[base + (size_t)(k0 + r) * MHA_D + c];
        }
        __syncthreads();

        // Scores: s[i][j] = Q[ty*4+i,:] . K[tx*4+j,:]
        float s[4][4];
        #pragma unroll
        for (int i = 0; i < 4; i++)
            #pragma unroll
            for (int j = 0; j < 4; j++) s[i][j] = 0.0f;

        #pragma unroll 16
        for (int d = 0; d < 64; d++) {
            float qv[4], kv[4];
            #pragma unroll
            for (int i = 0; i < 4; i++) qv[i] = Qs[(ty * 4 + i) * FA_AS + d];
            #pragma unroll
            for (int j = 0; j < 4; j++) kv[j] = Ks[(tx * 4 + j) * FA_AS + d];
            #pragma unroll
            for (int i = 0; i < 4; i++)
                #pragma unroll
                for (int j = 0; j < 4; j++)
                    s[i][j] = fmaf(qv[i], kv[j], s[i][j]);
        }

        const float sc = 0.125f;  // 1/sqrt(64)
        if (kt == ktmax) {
            #pragma unroll
            for (int i = 0; i < 4; i++)
                #pragma unroll
                for (int j = 0; j < 4; j++) {
                    int qg = q0 + ty * 4 + i;
                    int kg = k0 + tx * 4 + j;
                    s[i][j] = (kg > qg) ? -INFINITY : s[i][j] * sc;
                }
        } else {
            #pragma unroll
            for (int i = 0; i < 4; i++)
                #pragma unroll
                for (int j = 0; j < 4; j++) s[i][j] *= sc;
        }

        // Online softmax update (row reduction across the 16 tx lanes)
        #pragma unroll
        for (int i = 0; i < 4; i++) {
            float rm = fmaxf(fmaxf(s[i][0], s[i][1]), fmaxf(s[i][2], s[i][3]));
            #pragma unroll
            for (int off = 8; off >= 1; off >>= 1)
                rm = fmaxf(rm, __shfl_xor_sync(0xffffffffu, rm, off, 16));
            float mnew = fmaxf(m_i[i], rm);
            float corr = __expf(m_i[i] - mnew);
            float rsum = 0.0f;
            #pragma unroll
            for (int j = 0; j < 4; j++) {
                float p = __expf(s[i][j] - mnew);
                rsum += p;
                Ps[(ty * 4 + i) * FA_AS + tx * 4 + j] = p;
            }
            #pragma unroll
            for (int off = 8; off >= 1; off >>= 1)
                rsum += __shfl_xor_sync(0xffffffffu, rsum, off, 16);
            l_i[i] = l_i[i] * corr + rsum;
            m_i[i] = mnew;
            #pragma unroll
            for (int j = 0; j < 4; j++) o[i][j] *= corr;
        }
        __syncthreads();

        // PV: o[i][j] += P[ty*4+i, k] * V[k, tx*4+j]
        #pragma unroll 16
        for (int k = 0; k < 64; k++) {
            float pv[4], vv[4];
            #pragma unroll
            for (int i = 0; i < 4; i++) pv[i] = Ps[(ty * 4 + i) * FA_AS + k];
            #pragma unroll
            for (int j = 0; j < 4; j++) vv[j] = Vs[k * FA_AS + tx * 4 + j];
            #pragma unroll
            for (int i = 0; i < 4; i++)
                #pragma unroll
                for (int j = 0; j < 4; j++)
                    o[i][j] = fmaf(pv[i], vv[j], o[i][j]);
        }
        __syncthreads();
    }

    // Write ctx in [B,S,H,HD] layout
    #pragma unroll
    for (int i = 0; i < 4; i++) {
        const float inv = 1.0f / l_i[i];
        const int q = q0 + ty * 4 + i;
        const size_t off = (((size_t)b * MHA_S + q) * MHA_H + h) * MHA_HD + tx * 4;
        float4 v;
        v.x = o[i][0] * inv; v.y = o[i][1] * inv;
        v.z = o[i][2] * inv; v.w = o[i][3] * inv;
        *(float4*)&Og[off] = v;
    }
}

// ---------------------------------------------------------------------------
extern "C" void kernel_launch(void* const* d_in, const int* in_sizes, int n_in,
                              void* d_out, int out_size)
{
    const float* x  = (const float*)d_in[0];
    const float* Wq = (const float*)d_in[1];
    const float* Wk = (const float*)d_in[2];
    const float* Wv = (const float*)d_in[3];
    const float* Wo = (const float*)d_in[4];
    const float* bo = (const float*)d_in[5];
    float* out = (float*)d_out;

    float *Qb, *Kb, *Vb, *Cb;
    cudaGetSymbolAddress((void**)&Qb, g_Q);
    cudaGetSymbolAddress((void**)&Kb, g_K);
    cudaGetSymbolAddress((void**)&Vb, g_V);
    cudaGetSymbolAddress((void**)&Cb, g_C);

    const int fa_smem = 4 * 64 * FA_AS * (int)sizeof(float);  // 66560 B
    cudaFuncSetAttribute(flash_kernel,
                         cudaFuncAttributeMaxDynamicSharedMemorySize, fa_smem);

    dim3 gemm_grid(MHA_D / 128, NTOK / 128);  // (8, 32)
    dim3 gemm_blk(256);

    // QKV projections
    sgemm_kernel<false><<<gemm_grid, gemm_blk>>>(x, Wq, nullptr, Qb, NTOK, MHA_D, MHA_D);
    sgemm_kernel<false><<<gemm_grid, gemm_blk>>>(x, Wk, nullptr, Kb, NTOK, MHA_D, MHA_D);
    sgemm_kernel<false><<<gemm_grid, gemm_blk>>>(x, Wv, nullptr, Vb, NTOK, MHA_D, MHA_D);

    // Causal flash attention
    dim3 fa_grid(MHA_S / 64, MHA_B * MHA_H);  // (32, 32)
    flash_kernel<<<fa_grid, 256, fa_smem>>>(Qb, Kb, Vb, Cb);

    // Output projection with bias
    sgemm_kernel<true><<<gemm_grid, gemm_blk>>>(Cb, Wo, bo, out, NTOK, MHA_D, MHA_D);
}

// round 3
// speedup vs baseline: 1.4509x; 1.4509x over previous
#include <cuda_runtime.h>
#include <cuda_bf16.h>
#include <math.h>
#include <stdint.h>

#define MHA_B  2
#define MHA_S  2048
#define MHA_D  1024
#define MHA_H  16
#define MHA_HD 64
#define NTOK   (MHA_B * MHA_S)

// ---------------------------------------------------------------------------
// Scratch (__device__ globals; allocation-free rule)
// ---------------------------------------------------------------------------
__device__ float g_Q[NTOK * MHA_D];
__device__ float g_K[NTOK * MHA_D];
__device__ float g_V[NTOK * MHA_D];
__device__ float g_C[NTOK * MHA_D];

__device__ __nv_bfloat16 g_xhi[NTOK * MHA_D];
__device__ __nv_bfloat16 g_xlo[NTOK * MHA_D];
__device__ __nv_bfloat16 g_chi[NTOK * MHA_D];
__device__ __nv_bfloat16 g_clo[NTOK * MHA_D];

__device__ __nv_bfloat16 g_wqt_hi[MHA_D * MHA_D];
__device__ __nv_bfloat16 g_wqt_lo[MHA_D * MHA_D];
__device__ __nv_bfloat16 g_wkt_hi[MHA_D * MHA_D];
__device__ __nv_bfloat16 g_wkt_lo[MHA_D * MHA_D];
__device__ __nv_bfloat16 g_wvt_hi[MHA_D * MHA_D];
__device__ __nv_bfloat16 g_wvt_lo[MHA_D * MHA_D];
__device__ __nv_bfloat16 g_wot_hi[MHA_D * MHA_D];
__device__ __nv_bfloat16 g_wot_lo[MHA_D * MHA_D];

// ---------------------------------------------------------------------------
// Portable (sm_80+) tensor-core helpers: ldmatrix + mma.sync bf16
// ---------------------------------------------------------------------------
__device__ __forceinline__ uint32_t smem_u32(const void* p) {
    uint32_t a;
    asm("{ .reg .u64 t; cvta.to.shared.u64 t, %1; cvt.u32.u64 %0, t; }"
        : "=r"(a) : "l"(p));
    return a;
}

__device__ __forceinline__ void ldmx4(uint32_t* r, uint32_t addr) {
    asm volatile(
        "ldmatrix.sync.aligned.m8n8.x4.shared.b16 {%0,%1,%2,%3}, [%4];"
        : "=r"(r[0]), "=r"(r[1]), "=r"(r[2]), "=r"(r[3]) : "r"(addr));
}

__device__ __forceinline__ void mma16816(float* d, const uint32_t* a,
                                         uint32_t b0, uint32_t b1) {
    asm volatile(
        "mma.sync.aligned.m16n8k16.row.col.f32.bf16.bf16.f32 "
        "{%0,%1,%2,%3}, {%4,%5,%6,%7}, {%8,%9}, {%0,%1,%2,%3};"
        : "+f"(d[0]), "+f"(d[1]), "+f"(d[2]), "+f"(d[3])
        : "r"(a[0]), "r"(a[1]), "r"(a[2]), "r"(a[3]), "r"(b0), "r"(b1));
}

// SW128 swizzle on 128-byte rows: chunk' = chunk ^ (row & 7)
#define SWZ128(off) ((off) ^ (((off) >> 3) & 0x70))

// ---------------------------------------------------------------------------
// Conversion kernels
// ---------------------------------------------------------------------------
__global__ void split_kernel(const float* __restrict__ in,
                             __nv_bfloat16* __restrict__ hi,
                             __nv_bfloat16* __restrict__ lo)
{
    int i = (blockIdx.x * 256 + threadIdx.x) * 4;
    float4 v = *(const float4*)(in + i);
    __nv_bfloat16 h0 = __float2bfloat16(v.x);
    __nv_bfloat16 h1 = __float2bfloat16(v.y);
    __nv_bfloat16 h2 = __float2bfloat16(v.z);
    __nv_bfloat16 h3 = __float2bfloat16(v.w);
    __nv_bfloat16 l0 = __float2bfloat16(v.x - __bfloat162float(h0));
    __nv_bfloat16 l1 = __float2bfloat16(v.y - __bfloat162float(h1));
    __nv_bfloat16 l2 = __float2bfloat16(v.z - __bfloat162float(h2));
    __nv_bfloat16 l3 = __float2bfloat16(v.w - __bfloat162float(h3));
    ((__nv_bfloat162*)hi)[i / 2]     = __nv_bfloat162(h0, h1);
    ((__nv_bfloat162*)hi)[i / 2 + 1] = __nv_bfloat162(h2, h3);
    ((__nv_bfloat162*)lo)[i / 2]     = __nv_bfloat162(l0, l1);
    ((__nv_bfloat162*)lo)[i / 2 + 1] = __nv_bfloat162(l2, l3);
}

// W[K=1024][N=1024] fp32 -> WT_hi/lo[N][K] bf16 (transpose + split)
__global__ void transpose_split_kernel(const float* __restrict__ W,
                                       __nv_bfloat16* __restrict__ Thi,
                                       __nv_bfloat16* __restrict__ Tlo)
{
    __shared__ float t[32][33];
    const int tx = threadIdx.x, ty = threadIdx.y;
    const int k0 = blockIdx.y * 32;
    const int n0 = blockIdx.x * 32;
    #pragma unroll
    for (int j = 0; j < 4; j++)
        t[ty + j * 8][tx] = W[(size_t)(k0 + ty + j * 8) * MHA_D + n0 + tx];
    __syncthreads();
    #pragma unroll
    for (int j = 0; j < 4; j++) {
        float v = t[tx][ty + j * 8];
        __nv_bfloat16 h = __float2bfloat16(v);
        __nv_bfloat16 l = __float2bfloat16(v - __bfloat162float(h));
        size_t o = (size_t)(n0 + ty + j * 8) * MHA_D + k0 + tx;
        Thi[o] = h;
        Tlo[o] = l;
    }
}

// ---------------------------------------------------------------------------
// HMMA bf16-split GEMM: C[4096,1024] = A[4096,1024] * B[1024,1024] (+bias)
// A as (Ahi, Alo) row-major [M][K] bf16; B as (Bhi, Blo) = B^T [N][K] bf16.
// CTA: 128x128 C tile, BK=64. 8 warps in a 4(m) x 2(n) grid; warp tile 32x64.
// fp32 accumulation in register fragments via mma.sync m16n8k16.
// ---------------------------------------------------------------------------
#define GM_M 4096
#define GM_N 1024
#define GM_K 1024
#define GT_M 128
#define GT_N 128
#define GT_K 64

#define TILE_B (GT_M * GT_K * 2)           // 16384 bytes per bf16 tile
#define SM_AHI 0
#define SM_ALO (SM_AHI + TILE_B)
#define SM_BHI (SM_ALO + TILE_B)
#define SM_BLO (SM_BHI + TILE_B)
#define SM_GEMM_TOTAL (4 * TILE_B)         // 64 KB

template <bool BIAS>
__global__ __launch_bounds__(256, 1) void gemm_hmma_kernel(
    const __nv_bfloat16* __restrict__ Ahi, const __nv_bfloat16* __restrict__ Alo,
    const __nv_bfloat16* __restrict__ Bhi, const __nv_bfloat16* __restrict__ Blo,
    const float* __restrict__ bias, float* __restrict__ C)
{
    extern __shared__ char smem[];
    const uint32_t sbase = smem_u32(smem);
    const int tid = threadIdx.x;
    const int wid = tid >> 5;
    const int ln  = tid & 31;
    const int warp_m = wid >> 1;          // 0..3 (32 rows each)
    const int warp_n = wid & 1;           // 0..1 (64 cols each)
    const int m0 = blockIdx.y * GT_M;
    const int n0 = blockIdx.x * GT_N;

    float acc[2][8][4];
    #pragma unroll
    for (int i = 0; i < 2; i++)
        #pragma unroll
        for (int j = 0; j < 8; j++)
            #pragma unroll
            for (int q = 0; q < 4; q++) acc[i][j][q] = 0.0f;

    // ldmatrix row/half decomposition (same pattern for A and B tiles)
    const int lrow = ln & 15;             // row within 16-row group
    const int lhalf = ln >> 4;            // k-half (0: k0-7, 1: k8-15)

    // Per-mf A ldmatrix base rows; per-nfp B base rows
    int a_row[2], b_row[4];
    #pragma unroll
    for (int mf = 0; mf < 2; mf++) a_row[mf] = warp_m * 32 + mf * 16 + lrow;
    #pragma unroll
    for (int nf = 0; nf < 4; nf++) b_row[nf] = warp_n * 64 + nf * 16 + lrow;

    // Gmem loader indices: 1024 16B-chunks per tile, 256 threads -> 4 iters
    // chunk id = it*256 + tid: row = id>>3, c = id&7
    for (int kc = 0; kc < GM_K / GT_K; kc++) {
        const int k0 = kc * GT_K;
        __syncthreads();   // previous compute done before overwriting tiles
        #pragma unroll
        for (int it = 0; it < 4; it++) {
            const int id = it * 256 + tid;
            const int row = id >> 3;
            const int c = id & 7;
            const uint32_t so = SWZ128((uint32_t)(row * 128 + c * 16));
            const size_t ga = (size_t)(m0 + row) * GM_K + k0 + c * 8;
            const size_t gb = (size_t)(n0 + row) * GM_K + k0 + c * 8;
            *(uint4*)(smem + SM_AHI + so) = *(const uint4*)(Ahi + ga);
            *(uint4*)(smem + SM_ALO + so) = *(const uint4*)(Alo + ga);
            *(uint4*)(smem + SM_BHI + so) = *(const uint4*)(Bhi + gb);
            *(uint4*)(smem + SM_BLO + so) = *(const uint4*)(Blo + gb);
        }
        __syncthreads();

        #pragma unroll
        for (int ks = 0; ks < 4; ks++) {
            const int chunk = ks * 2 + lhalf;
            uint32_t ah[2][4], al[2][4];
            #pragma unroll
            for (int mf = 0; mf < 2; mf++) {
                const int r = a_row[mf];
                const uint32_t off = (uint32_t)(r * 128 + ((chunk ^ (r & 7)) << 4));
                ldmx4(ah[mf], sbase + SM_AHI + off);
                ldmx4(al[mf], sbase + SM_ALO + off);
            }
            uint32_t bh[4][4], bl[4][4];
            #pragma unroll
            for (int nf = 0; nf < 4; nf++) {
                const int r = b_row[nf];
                const uint32_t off = (uint32_t)(r * 128 + ((chunk ^ (r & 7)) << 4));
                ldmx4(bh[nf], sbase + SM_BHI + off);
                ldmx4(bl[nf], sbase + SM_BLO + off);
            }
            // mma: 2 mfrag x 8 nfrag x {hi*hi, hi*lo, lo*hi}
            #pragma unroll
            for (int mf = 0; mf < 2; mf++) {
                #pragma unroll
                for (int nf = 0; nf < 8; nf++) {
                    const int nfp = nf >> 1;
                    const int odd = nf & 1;
                    mma16816(acc[mf][nf], ah[mf], bh[nfp][odd], bh[nfp][2 + odd]);
                    mma16816(acc[mf][nf], ah[mf], bl[nfp][odd], bl[nfp][2 + odd]);
                    mma16816(acc[mf][nf], al[mf], bh[nfp][odd], bh[nfp][2 + odd]);
                }
            }
        }
    }

    // Epilogue: c0,c1 -> (row gid, col 2*tig); c2,c3 -> (row gid+8)
    const int gid = ln >> 2;
    const int tig = ln & 3;
    #pragma unroll
    for (int mf = 0; mf < 2; mf++) {
        #pragma unroll
        for (int nf = 0; nf < 8; nf++) {
            const int col = n0 + warp_n * 64 + nf * 8 + tig * 2;
            const int r0 = m0 + warp_m * 32 + mf * 16 + gid;
            float2 v0, v1;
            v0.x = acc[mf][nf][0]; v0.y = acc[mf][nf][1];
            v1.x = acc[mf][nf][2]; v1.y = acc[mf][nf][3];
            if (BIAS) {
                const float b0v = bias[col], b1v = bias[col + 1];
                v0.x += b0v; v0.y += b1v;
                v1.x += b0v; v1.y += b1v;
            }
            *(float2*)(C + (size_t)r0 * GM_N + col) = v0;
            *(float2*)(C + (size_t)(r0 + 8) * GM_N + col) = v1;
        }
    }
}

// ---------------------------------------------------------------------------
// Flash attention, fp32, causal (unchanged).
// ---------------------------------------------------------------------------
#define FA_AS 65

__global__ __launch_bounds__(256) void flash_kernel(
    const float* __restrict__ Qg, const float* __restrict__ Kg,
    const float* __restrict__ Vg, float* __restrict__ Og)
{
    extern __shared__ float sm[];
    float* Qs = sm;
    float* Ks = sm + 64 * FA_AS;
    float* Vs = sm + 2 * 64 * FA_AS;
    float* Ps = sm + 3 * 64 * FA_AS;

    const int tid = threadIdx.x;
    const int tx = tid & 15;
    const int ty = tid >> 4;
    const int b  = blockIdx.y >> 4;
    const int h  = blockIdx.y & 15;
    const int q0 = blockIdx.x * 64;
    const size_t base = (size_t)b * MHA_S * MHA_D + (size_t)h * MHA_HD;

    #pragma unroll
    for (int i = 0; i < 16; i++) {
        int idx = i * 256 + tid;
        int r = idx >> 6, c = idx & 63;
        Qs[r * FA_AS + c] = Qg[base + (size_t)(q0 + r) * MHA_D + c];
    }

    float m_i[4], l_i[4], o[4][4];
    #pragma unroll
    for (int i = 0; i < 4; i++) {
        m_i[i] = -1e30f;
        l_i[i] = 0.0f;
        #pragma unroll
        for (int j = 0; j < 4; j++) o[i][j] = 0.0f;
    }
    __syncthreads();

    const int ktmax = blockIdx.x;
    for (int kt = 0; kt <= ktmax; kt++) {
        const int k0 = kt * 64;
        #pragma unroll
        for (int i = 0; i < 16; i++) {
            int idx = i * 256 + tid;
            int r = idx >> 6, c = idx & 63;
            Ks[r * FA_AS + c] = Kg[base + (size_t)(k0 + r) * MHA_D + c];
            Vs[r * FA_AS + c] = Vg[base + (size_t)(k0 + r) * MHA_D + c];
        }
        __syncthreads();

        float s[4][4];
        #pragma unroll
        for (int i = 0; i < 4; i++)
            #pragma unroll
            for (int j = 0; j < 4; j++) s[i][j] = 0.0f;

        #pragma unroll 16
        for (int d = 0; d < 64; d++) {
            float qv[4], kv[4];
            #pragma unroll
            for (int i = 0; i < 4; i++) qv[i] = Qs[(ty * 4 + i) * FA_AS + d];
            #pragma unroll
            for (int j = 0; j < 4; j++) kv[j] = Ks[(tx * 4 + j) * FA_AS + d];
            #pragma unroll
            for (int i = 0; i < 4; i++)
                #pragma unroll
                for (int j = 0; j < 4; j++)
                    s[i][j] = fmaf(qv[i], kv[j], s[i][j]);
        }

        const float sc = 0.125f;
        if (kt == ktmax) {
            #pragma unroll
            for (int i = 0; i < 4; i++)
                #pragma unroll
                for (int j = 0; j < 4; j++) {
                    int qg = q0 + ty * 4 + i;
                    int kg = k0 + tx * 4 + j;
                    s[i][j] = (kg > qg) ? -INFINITY : s[i][j] * sc;
                }
        } else {
            #pragma unroll
            for (int i = 0; i < 4; i++)
                #pragma unroll
                for (int j = 0; j < 4; j++) s[i][j] *= sc;
        }

        #pragma unroll
        for (int i = 0; i < 4; i++) {
            float rm = fmaxf(fmaxf(s[i][0], s[i][1]), fmaxf(s[i][2], s[i][3]));
            #pragma unroll
            for (int off = 8; off >= 1; off >>= 1)
                rm = fmaxf(rm, __shfl_xor_sync(0xffffffffu, rm, off, 16));
            float mnew = fmaxf(m_i[i], rm);
            float corr = __expf(m_i[i] - mnew);
            float rsum = 0.0f;
            #pragma unroll
            for (int j = 0; j < 4; j++) {
                float p = __expf(s[i][j] - mnew);
                rsum += p;
                Ps[(ty * 4 + i) * FA_AS + tx * 4 + j] = p;
            }
            #pragma unroll
            for (int off = 8; off >= 1; off >>= 1)
                rsum += __shfl_xor_sync(0xffffffffu, rsum, off, 16);
            l_i[i] = l_i[i] * corr + rsum;
            m_i[i] = mnew;
            #pragma unroll
            for (int j = 0; j < 4; j++) o[i][j] *= corr;
        }
        __syncthreads();

        #pragma unroll 16
        for (int k = 0; k < 64; k++) {
            float pv[4], vv[4];
            #pragma unroll
            for (int i = 0; i < 4; i++) pv[i] = Ps[(ty * 4 + i) * FA_AS + k];
            #pragma unroll
            for (int j = 0; j < 4; j++) vv[j] = Vs[k * FA_AS + tx * 4 + j];
            #pragma unroll
            for (int i = 0; i < 4; i++)
                #pragma unroll
                for (int j = 0; j < 4; j++)
                    o[i][j] = fmaf(pv[i], vv[j], o[i][j]);
        }
        __syncthreads();
    }

    #pragma unroll
    for (int i = 0; i < 4; i++) {
        const float inv = 1.0f / l_i[i];
        const int q = q0 + ty * 4 + i;
        const size_t off = (((size_t)b * MHA_S + q) * MHA_H + h) * MHA_HD + tx * 4;
        float4 v;
        v.x = o[i][0] * inv; v.y = o[i][1] * inv;
        v.z = o[i][2] * inv; v.w = o[i][3] * inv;
        *(float4*)&Og[off] = v;
    }
}

// ---------------------------------------------------------------------------
extern "C" void kernel_launch(void* const* d_in, const int* in_sizes, int n_in,
                              void* d_out, int out_size)
{
    const float* x  = (const float*)d_in[0];
    const float* Wq = (const float*)d_in[1];
    const float* Wk = (const float*)d_in[2];
    const float* Wv = (const float*)d_in[3];
    const float* Wo = (const float*)d_in[4];
    const float* bo = (const float*)d_in[5];
    float* out = (float*)d_out;

    float *Qb, *Kb, *Vb, *Cb;
    cudaGetSymbolAddress((void**)&Qb, g_Q);
    cudaGetSymbolAddress((void**)&Kb, g_K);
    cudaGetSymbolAddress((void**)&Vb, g_V);
    cudaGetSymbolAddress((void**)&Cb, g_C);

    __nv_bfloat16 *xhi, *xlo, *chi, *clo;
    __nv_bfloat16 *wqh, *wql, *wkh, *wkl, *wvh, *wvl, *woh, *wol;
    cudaGetSymbolAddress((void**)&xhi, g_xhi);
    cudaGetSymbolAddress((void**)&xlo, g_xlo);
    cudaGetSymbolAddress((void**)&chi, g_chi);
    cudaGetSymbolAddress((void**)&clo, g_clo);
    cudaGetSymbolAddress((void**)&wqh, g_wqt_hi);
    cudaGetSymbolAddress((void**)&wql, g_wqt_lo);
    cudaGetSymbolAddress((void**)&wkh, g_wkt_hi);
    cudaGetSymbolAddress((void**)&wkl, g_wkt_lo);
    cudaGetSymbolAddress((void**)&wvh, g_wvt_hi);
    cudaGetSymbolAddress((void**)&wvl, g_wvt_lo);
    cudaGetSymbolAddress((void**)&woh, g_wot_hi);
    cudaGetSymbolAddress((void**)&wol, g_wot_lo);

    const int fa_smem = 4 * 64 * FA_AS * (int)sizeof(float);
    cudaFuncSetAttribute(flash_kernel,
                         cudaFuncAttributeMaxDynamicSharedMemorySize, fa_smem);
    cudaFuncSetAttribute(gemm_hmma_kernel<false>,
                         cudaFuncAttributeMaxDynamicSharedMemorySize, SM_GEMM_TOTAL);
    cudaFuncSetAttribute(gemm_hmma_kernel<true>,
                         cudaFuncAttributeMaxDynamicSharedMemorySize, SM_GEMM_TOTAL);

    // Convert inputs: x -> bf16 hi/lo; weights -> transposed bf16 hi/lo
    split_kernel<<<NTOK * MHA_D / 1024, 256>>>(x, xhi, xlo);
    dim3 tgrid(MHA_D / 32, MHA_D / 32), tblk(32, 8);
    transpose_split_kernel<<<tgrid, tblk>>>(Wq, wqh, wql);
    transpose_split_kernel<<<tgrid, tblk>>>(Wk, wkh, wkl);
    transpose_split_kernel<<<tgrid, tblk>>>(Wv, wvh, wvl);
    transpose_split_kernel<<<tgrid, tblk>>>(Wo, woh, wol);

    // QKV projections on tensor cores (HMMA)
    dim3 ggrid(GM_N / GT_N, GM_M / GT_M);  // (8, 32)
    gemm_hmma_kernel<false><<<ggrid, 256, SM_GEMM_TOTAL>>>(xhi, xlo, wqh, wql, nullptr, Qb);
    gemm_hmma_kernel<false><<<ggrid, 256, SM_GEMM_TOTAL>>>(xhi, xlo, wkh, wkl, nullptr, Kb);
    gemm_hmma_kernel<false><<<ggrid, 256, SM_GEMM_TOTAL>>>(xhi, xlo, wvh, wvl, nullptr, Vb);

    // Causal flash attention (fp32)
    dim3 fa_grid(MHA_S / 64, MHA_B * MHA_H);
    flash_kernel<<<fa_grid, 256, fa_smem>>>(Qb, Kb, Vb, Cb);

    // Output projection with bias
    split_kernel<<<NTOK * MHA_D / 1024, 256>>>(Cb, chi, clo);
    gemm_hmma_kernel<true><<<ggrid, 256, SM_GEMM_TOTAL>>>(chi, clo, woh, wol, bo, out);
}

// round 4
// speedup vs baseline: 2.4720x; 1.7038x over previous
#include <cuda_runtime.h>
#include <cuda_bf16.h>
#include <math.h>
#include <stdint.h>

#define MHA_B  2
#define MHA_S  2048
#define MHA_D  1024
#define MHA_H  16
#define MHA_HD 64
#define NTOK   (MHA_B * MHA_S)

// ---------------------------------------------------------------------------
// Scratch (__device__ globals; allocation-free rule)
// ---------------------------------------------------------------------------
__device__ __nv_bfloat16 g_xhi[NTOK * MHA_D];
__device__ __nv_bfloat16 g_xlo[NTOK * MHA_D];

__device__ __nv_bfloat16 g_qhi[NTOK * MHA_D];
__device__ __nv_bfloat16 g_qlo[NTOK * MHA_D];
__device__ __nv_bfloat16 g_khi[NTOK * MHA_D];
__device__ __nv_bfloat16 g_klo[NTOK * MHA_D];
__device__ __nv_bfloat16 g_vhi[NTOK * MHA_D];
__device__ __nv_bfloat16 g_vlo[NTOK * MHA_D];
__device__ __nv_bfloat16 g_chi[NTOK * MHA_D];
__device__ __nv_bfloat16 g_clo[NTOK * MHA_D];

__device__ __nv_bfloat16 g_wqt_hi[MHA_D * MHA_D];
__device__ __nv_bfloat16 g_wqt_lo[MHA_D * MHA_D];
__device__ __nv_bfloat16 g_wkt_hi[MHA_D * MHA_D];
__device__ __nv_bfloat16 g_wkt_lo[MHA_D * MHA_D];
__device__ __nv_bfloat16 g_wvt_hi[MHA_D * MHA_D];
__device__ __nv_bfloat16 g_wvt_lo[MHA_D * MHA_D];
__device__ __nv_bfloat16 g_wot_hi[MHA_D * MHA_D];
__device__ __nv_bfloat16 g_wot_lo[MHA_D * MHA_D];

// ---------------------------------------------------------------------------
// Portable (sm_80+) tensor-core helpers
// ---------------------------------------------------------------------------
__device__ __forceinline__ uint32_t smem_u32(const void* p) {
    uint32_t a;
    asm("{ .reg .u64 t; cvta.to.shared.u64 t, %1; cvt.u32.u64 %0, t; }"
        : "=r"(a) : "l"(p));
    return a;
}

__device__ __forceinline__ void ldmx4(uint32_t* r, uint32_t addr) {
    asm volatile(
        "ldmatrix.sync.aligned.m8n8.x4.shared.b16 {%0,%1,%2,%3}, [%4];"
        : "=r"(r[0]), "=r"(r[1]), "=r"(r[2]), "=r"(r[3]) : "r"(addr));
}

__device__ __forceinline__ void ldmx4t(uint32_t* r, uint32_t addr) {
    asm volatile(
        "ldmatrix.sync.aligned.m8n8.x4.trans.shared.b16 {%0,%1,%2,%3}, [%4];"
        : "=r"(r[0]), "=r"(r[1]), "=r"(r[2]), "=r"(r[3]) : "r"(addr));
}

__device__ __forceinline__ void mma16816(float* d, const uint32_t* a,
                                         uint32_t b0, uint32_t b1) {
    asm volatile(
        "mma.sync.aligned.m16n8k16.row.col.f32.bf16.bf16.f32 "
        "{%0,%1,%2,%3}, {%4,%5,%6,%7}, {%8,%9}, {%0,%1,%2,%3};"
        : "+f"(d[0]), "+f"(d[1]), "+f"(d[2]), "+f"(d[3])
        : "r"(a[0]), "r"(a[1]), "r"(a[2]), "r"(a[3]), "r"(b0), "r"(b1));
}

#define SWZ128(off) ((off) ^ (((off) >> 3) & 0x70))

// ---------------------------------------------------------------------------
// Conversion kernels
// ---------------------------------------------------------------------------
__global__ void split_kernel(const float* __restrict__ in,
                             __nv_bfloat16* __restrict__ hi,
                             __nv_bfloat16* __restrict__ lo)
{
    int i = (blockIdx.x * 256 + threadIdx.x) * 4;
    float4 v = *(const float4*)(in + i);
    __nv_bfloat16 h0 = __float2bfloat16(v.x);
    __nv_bfloat16 h1 = __float2bfloat16(v.y);
    __nv_bfloat16 h2 = __float2bfloat16(v.z);
    __nv_bfloat16 h3 = __float2bfloat16(v.w);
    __nv_bfloat16 l0 = __float2bfloat16(v.x - __bfloat162float(h0));
    __nv_bfloat16 l1 = __float2bfloat16(v.y - __bfloat162float(h1));
    __nv_bfloat16 l2 = __float2bfloat16(v.z - __bfloat162float(h2));
    __nv_bfloat16 l3 = __float2bfloat16(v.w - __bfloat162float(h3));
    ((__nv_bfloat162*)hi)[i / 2]     = __nv_bfloat162(h0, h1);
    ((__nv_bfloat162*)hi)[i / 2 + 1] = __nv_bfloat162(h2, h3);
    ((__nv_bfloat162*)lo)[i / 2]     = __nv_bfloat162(l0, l1);
    ((__nv_bfloat162*)lo)[i / 2 + 1] = __nv_bfloat162(l2, l3);
}

__global__ void transpose_split_kernel(const float* __restrict__ W,
                                       __nv_bfloat16* __restrict__ Thi,
                                       __nv_bfloat16* __restrict__ Tlo)
{
    __shared__ float t[32][33];
    const int tx = threadIdx.x, ty = threadIdx.y;
    const int k0 = blockIdx.y * 32;
    const int n0 = blockIdx.x * 32;
    #pragma unroll
    for (int j = 0; j < 4; j++)
        t[ty + j * 8][tx] = W[(size_t)(k0 + ty + j * 8) * MHA_D + n0 + tx];
    __syncthreads();
    #pragma unroll
    for (int j = 0; j < 4; j++) {
        float v = t[tx][ty + j * 8];
        __nv_bfloat16 h = __float2bfloat16(v);
        __nv_bfloat16 l = __float2bfloat16(v - __bfloat162float(h));
        size_t o = (size_t)(n0 + ty + j * 8) * MHA_D + k0 + tx;
        Thi[o] = h;
        Tlo[o] = l;
    }
}

// ---------------------------------------------------------------------------
// HMMA bf16-split GEMM: C = A * B (+bias), optional split-bf16 output.
// A as (Ahi, Alo) row-major [M][K]; B as (Bhi, Blo) = B^T [N][K].
// CTA: 128x128 tile, BK=64, 8 warps 4(m)x2(n), warp tile 32x64.
// ---------------------------------------------------------------------------
#define GM_M 4096
#define GM_N 1024
#define GM_K 1024
#define GT_M 128
#define GT_N 128
#define GT_K 64

#define TILE_B (GT_M * GT_K * 2)
#define SM_AHI 0
#define SM_ALO (SM_AHI + TILE_B)
#define SM_BHI (SM_ALO + TILE_B)
#define SM_BLO (SM_BHI + TILE_B)
#define SM_GEMM_TOTAL (4 * TILE_B)   // 64 KB

template <bool SPLIT, bool BIAS>
__global__ __launch_bounds__(256, 1) void gemm_hmma_kernel(
    const __nv_bfloat16* __restrict__ Ahi, const __nv_bfloat16* __restrict__ Alo,
    const __nv_bfloat16* __restrict__ Bhi, const __nv_bfloat16* __restrict__ Blo,
    const float* __restrict__ bias, float* __restrict__ C,
    __nv_bfloat16* __restrict__ Ohi, __nv_bfloat16* __restrict__ Olo,
    float scale)
{
    extern __shared__ char smem[];
    const uint32_t sbase = smem_u32(smem);
    const int tid = threadIdx.x;
    const int wid = tid >> 5;
    const int ln  = tid & 31;
    const int warp_m = wid >> 1;
    const int warp_n = wid & 1;
    const int m0 = blockIdx.y * GT_M;
    const int n0 = blockIdx.x * GT_N;

    float acc[2][8][4];
    #pragma unroll
    for (int i = 0; i < 2; i++)
        #pragma unroll
        for (int j = 0; j < 8; j++)
            #pragma unroll
            for (int q = 0; q < 4; q++) acc[i][j][q] = 0.0f;

    const int lrow = ln & 15;
    const int lhalf = ln >> 4;

    int a_row[2], b_row[4];
    #pragma unroll
    for (int mf = 0; mf < 2; mf++) a_row[mf] = warp_m * 32 + mf * 16 + lrow;
    #pragma unroll
    for (int nf = 0; nf < 4; nf++) b_row[nf] = warp_n * 64 + nf * 16 + lrow;

    for (int kc = 0; kc < GM_K / GT_K; kc++) {
        const int k0 = kc * GT_K;
        __syncthreads();
        #pragma unroll
        for (int it = 0; it < 4; it++) {
            const int id = it * 256 + tid;
            const int row = id >> 3;
            const int c = id & 7;
            const uint32_t so = SWZ128((uint32_t)(row * 128 + c * 16));
            const size_t ga = (size_t)(m0 + row) * GM_K + k0 + c * 8;
            const size_t gb = (size_t)(n0 + row) * GM_K + k0 + c * 8;
            *(uint4*)(smem + SM_AHI + so) = *(const uint4*)(Ahi + ga);
            *(uint4*)(smem + SM_ALO + so) = *(const uint4*)(Alo + ga);
            *(uint4*)(smem + SM_BHI + so) = *(const uint4*)(Bhi + gb);
            *(uint4*)(smem + SM_BLO + so) = *(const uint4*)(Blo + gb);
        }
        __syncthreads();

        #pragma unroll
        for (int ks = 0; ks < 4; ks++) {
            const int chunk = ks * 2 + lhalf;
            uint32_t ah[2][4], al[2][4];
            #pragma unroll
            for (int mf = 0; mf < 2; mf++) {
                const int r = a_row[mf];
                const uint32_t off = (uint32_t)(r * 128 + ((chunk ^ (r & 7)) << 4));
                ldmx4(ah[mf], sbase + SM_AHI + off);
                ldmx4(al[mf], sbase + SM_ALO + off);
            }
            uint32_t bh[4][4], bl[4][4];
            #pragma unroll
            for (int nf = 0; nf < 4; nf++) {
                const int r = b_row[nf];
                const uint32_t off = (uint32_t)(r * 128 + ((chunk ^ (r & 7)) << 4));
                ldmx4(bh[nf], sbase + SM_BHI + off);
                ldmx4(bl[nf], sbase + SM_BLO + off);
            }
            #pragma unroll
            for (int mf = 0; mf < 2; mf++) {
                #pragma unroll
                for (int nf = 0; nf < 8; nf++) {
                    const int nfp = nf >> 1;
                    const int odd = nf & 1;
                    mma16816(acc[mf][nf], ah[mf], bh[nfp][odd], bh[nfp][2 + odd]);
                    mma16816(acc[mf][nf], ah[mf], bl[nfp][odd], bl[nfp][2 + odd]);
                    mma16816(acc[mf][nf], al[mf], bh[nfp][odd], bh[nfp][2 + odd]);
                }
            }
        }
    }

    const int gid = ln >> 2;
    const int tig = ln & 3;
    #pragma unroll
    for (int mf = 0; mf < 2; mf++) {
        #pragma unroll
        for (int nf = 0; nf < 8; nf++) {
            const int col = n0 + warp_n * 64 + nf * 8 + tig * 2;
            const int r0 = m0 + warp_m * 32 + mf * 16 + gid;
            float2 v0, v1;
            v0.x = acc[mf][nf][0]; v0.y = acc[mf][nf][1];
            v1.x = acc[mf][nf][2]; v1.y = acc[mf][nf][3];
            if (SPLIT) {
                v0.x *= scale; v0.y *= scale; v1.x *= scale; v1.y *= scale;
                __nv_bfloat162 h0 = __float22bfloat162_rn(v0);
                __nv_bfloat162 h1 = __float22bfloat162_rn(v1);
                float2 r0v, r1v;
                r0v.x = v0.x - __bfloat162float(h0.x);
                r0v.y = v0.y - __bfloat162float(h0.y);
                r1v.x = v1.x - __bfloat162float(h1.x);
                r1v.y = v1.y - __bfloat162float(h1.y);
                __nv_bfloat162 l0b = __float22bfloat162_rn(r0v);
                __nv_bfloat162 l1b = __float22bfloat162_rn(r1v);
                *(__nv_bfloat162*)(Ohi + (size_t)r0 * GM_N + col) = h0;
                *(__nv_bfloat162*)(Olo + (size_t)r0 * GM_N + col) = l0b;
                *(__nv_bfloat162*)(Ohi + (size_t)(r0 + 8) * GM_N + col) = h1;
                *(__nv_bfloat162*)(Olo + (size_t)(r0 + 8) * GM_N + col) = l1b;
            } else {
                if (BIAS) {
                    const float b0v = bias[col], b1v = bias[col + 1];
                    v0.x += b0v; v0.y += b1v;
                    v1.x += b0v; v1.y += b1v;
                }
                *(float2*)(C + (size_t)r0 * GM_N + col) = v0;
                *(float2*)(C + (size_t)(r0 + 8) * GM_N + col) = v1;
            }
        }
    }
}

// ---------------------------------------------------------------------------
// Tensor-core flash attention, causal, bf16-split.
// CTA: 64 queries of one (b,h); 4 warps x 16 q-rows; K/V tiles of 64 keys.
// Q pre-scaled by 1/sqrt(HD) at production. Inputs/outputs bf16 hi/lo pairs
// in [NTOK][1024] layout (head h at cols h*64..h*64+63).
// ---------------------------------------------------------------------------
#define SF_QHI 0
#define SF_QLO 8192
#define SF_KHI 16384
#define SF_KLO 24576
#define SF_VHI 32768
#define SF_VLO 40960
#define SF_TOTAL 49152   // 48 KB

__global__ __launch_bounds__(128, 4) void flash_tc_kernel(
    const __nv_bfloat16* __restrict__ Qhi, const __nv_bfloat16* __restrict__ Qlo,
    const __nv_bfloat16* __restrict__ Khi, const __nv_bfloat16* __restrict__ Klo,
    const __nv_bfloat16* __restrict__ Vhi, const __nv_bfloat16* __restrict__ Vlo,
    __nv_bfloat16* __restrict__ Chi, __nv_bfloat16* __restrict__ Clo)
{
    extern __shared__ char smem[];
    const uint32_t sbase = smem_u32(smem);
    const int tid = threadIdx.x;
    const int wid = tid >> 5;
    const int ln  = tid & 31;
    const int b   = blockIdx.y >> 4;
    const int h   = blockIdx.y & 15;
    const int q0  = blockIdx.x * 64;
    const size_t base = (size_t)b * MHA_S * MHA_D + (size_t)h * MHA_HD;

    const int lrow  = ln & 15;
    const int lhalf = ln >> 4;
    const int gid   = ln >> 2;
    const int tig   = ln & 3;
    const int arow  = wid * 16 + lrow;

    // Load Q tile (64 x 64 bf16, hi+lo), SW128 swizzled 128B rows
    #pragma unroll
    for (int it = 0; it < 4; it++) {
        const int id = it * 128 + tid;
        const int r = id >> 3;
        const int c = id & 7;
        const uint32_t so = SWZ128((uint32_t)(r * 128 + c * 16));
        const size_t g = base + (size_t)(q0 + r) * MHA_D + c * 8;
        *(uint4*)(smem + SF_QHI + so) = *(const uint4*)(Qhi + g);
        *(uint4*)(smem + SF_QLO + so) = *(const uint4*)(Qlo + g);
    }

    float m0 = -1e30f, m1 = -1e30f, l0 = 0.0f, l1 = 0.0f;
    float o[8][4];
    #pragma unroll
    for (int nf = 0; nf < 8; nf++)
        #pragma unroll
        for (int q = 0; q < 4; q++) o[nf][q] = 0.0f;

    const int row0 = q0 + wid * 16 + gid;
    const int row1 = row0 + 8;

    for (int kt = 0; kt <= blockIdx.x; kt++) {
        const int k0 = kt * 64;
        __syncthreads();
        #pragma unroll
        for (int it = 0; it < 4; it++) {
            const int id = it * 128 + tid;
            const int r = id >> 3;
            const int c = id & 7;
            const uint32_t so = SWZ128((uint32_t)(r * 128 + c * 16));
            const size_t g = base + (size_t)(k0 + r) * MHA_D + c * 8;
            *(uint4*)(smem + SF_KHI + so) = *(const uint4*)(Khi + g);
            *(uint4*)(smem + SF_KLO + so) = *(const uint4*)(Klo + g);
            *(uint4*)(smem + SF_VHI + so) = *(const uint4*)(Vhi + g);
            *(uint4*)(smem + SF_VLO + so) = *(const uint4*)(Vlo + g);
        }
        __syncthreads();

        // ---- S = Q K^T (pre-scaled) ----
        float s[8][4];
        #pragma unroll
        for (int nf = 0; nf < 8; nf++)
            #pragma unroll
            for (int q = 0; q < 4; q++) s[nf][q] = 0.0f;

        #pragma unroll
        for (int ks = 0; ks < 4; ks++) {
            const int chunk = ks * 2 + lhalf;
            const uint32_t offA = (uint32_t)(arow * 128 + ((chunk ^ (arow & 7)) << 4));
            uint32_t ah[4], al[4];
            ldmx4(ah, sbase + SF_QHI + offA);
            ldmx4(al, sbase + SF_QLO + offA);
            #pragma unroll
            for (int nfp = 0; nfp < 4; nfp++) {
                const int brow = nfp * 16 + lrow;
                const uint32_t offB = (uint32_t)(brow * 128 + ((chunk ^ (brow & 7)) << 4));
                uint32_t bh[4], bl[4];
                ldmx4(bh, sbase + SF_KHI + offB);
                ldmx4(bl, sbase + SF_KLO + offB);
                #pragma unroll
                for (int odd = 0; odd < 2; odd++) {
                    const int nf = nfp * 2 + odd;
                    mma16816(s[nf], ah, bh[odd], bh[2 + odd]);
                    mma16816(s[nf], ah, bl[odd], bl[2 + odd]);
                    mma16816(s[nf], al, bh[odd], bh[2 + odd]);
                }
            }
        }

        // ---- causal mask (diagonal tile only) ----
        if (kt == blockIdx.x) {
            #pragma unroll
            for (int nf = 0; nf < 8; nf++) {
                const int c0 = k0 + nf * 8 + tig * 2;
                if (c0 > row0)     s[nf][0] = -INFINITY;
                if (c0 + 1 > row0) s[nf][1] = -INFINITY;
                if (c0 > row1)     s[nf][2] = -INFINITY;
                if (c0 + 1 > row1) s[nf][3] = -INFINITY;
            }
        }

        // ---- online softmax ----
        float mx0 = m0, mx1 = m1;
        #pragma unroll
        for (int nf = 0; nf < 8; nf++) {
            mx0 = fmaxf(mx0, fmaxf(s[nf][0], s[nf][1]));
            mx1 = fmaxf(mx1, fmaxf(s[nf][2], s[nf][3]));
        }
        mx0 = fmaxf(mx0, __shfl_xor_sync(0xffffffffu, mx0, 1));
        mx0 = fmaxf(mx0, __shfl_xor_sync(0xffffffffu, mx0, 2));
        mx1 = fmaxf(mx1, __shfl_xor_sync(0xffffffffu, mx1, 1));
        mx1 = fmaxf(mx1, __shfl_xor_sync(0xffffffffu, mx1, 2));

        const float corr0 = __expf(m0 - mx0);
        const float corr1 = __expf(m1 - mx1);
        m0 = mx0; m1 = mx1;

        float sum0 = 0.0f, sum1 = 0.0f;
        uint32_t ph[8][2], pl[8][2];
        #pragma unroll
        for (int nf = 0; nf < 8; nf++) {
            float2 p01, p23;
            p01.x = __expf(s[nf][0] - mx0);
            p01.y = __expf(s[nf][1] - mx0);
            p23.x = __expf(s[nf][2] - mx1);
            p23.y = __expf(s[nf][3] - mx1);
            sum0 += p01.x + p01.y;
            sum1 += p23.x + p23.y;
            __nv_bfloat162 h01 = __float22bfloat162_rn(p01);
            __nv_bfloat162 h23 = __float22bfloat162_rn(p23);
            float2 r01, r23;
            r01.x = p01.x - __bfloat162float(h01.x);
            r01.y = p01.y - __bfloat162float(h01.y);
            r23.x = p23.x - __bfloat162float(h23.x);
            r23.y = p23.y - __bfloat162float(h23.y);
            __nv_bfloat162 lo01 = __float22bfloat162_rn(r01);
            __nv_bfloat162 lo23 = __float22bfloat162_rn(r23);
            ph[nf][0] = *(uint32_t*)&h01;
            ph[nf][1] = *(uint32_t*)&h23;
            pl[nf][0] = *(uint32_t*)&lo01;
            pl[nf][1] = *(uint32_t*)&lo23;
        }
        sum0 += __shfl_xor_sync(0xffffffffu, sum0, 1);
        sum0 += __shfl_xor_sync(0xffffffffu, sum0, 2);
        sum1 += __shfl_xor_sync(0xffffffffu, sum1, 1);
        sum1 += __shfl_xor_sync(0xffffffffu, sum1, 2);
        l0 = l0 * corr0 + sum0;
        l1 = l1 * corr1 + sum1;

        #pragma unroll
        for (int nf = 0; nf < 8; nf++) {
            o[nf][0] *= corr0; o[nf][1] *= corr0;
            o[nf][2] *= corr1; o[nf][3] *= corr1;
        }

        // ---- O += P V ----
        #pragma unroll
        for (int kc = 0; kc < 4; kc++) {
            uint32_t aph[4], apl[4];
            aph[0] = ph[2 * kc][0];     aph[1] = ph[2 * kc][1];
            aph[2] = ph[2 * kc + 1][0]; aph[3] = ph[2 * kc + 1][1];
            apl[0] = pl[2 * kc][0];     apl[1] = pl[2 * kc][1];
            apl[2] = pl[2 * kc + 1][0]; apl[3] = pl[2 * kc + 1][1];
            const int g = ln >> 3;
            const int r8 = ln & 7;
            const int key = kc * 16 + (g & 1) * 8 + r8;
            #pragma unroll
            for (int hp = 0; hp < 4; hp++) {
                const int chunk = hp * 2 + (g >> 1);
                const uint32_t offV = (uint32_t)(key * 128 + ((chunk ^ (key & 7)) << 4));
                uint32_t vh[4], vl[4];
                ldmx4t(vh, sbase + SF_VHI + offV);
                ldmx4t(vl, sbase + SF_VLO + offV);
                mma16816(o[2 * hp], aph, vh[0], vh[1]);
                mma16816(o[2 * hp], aph, vl[0], vl[1]);
                mma16816(o[2 * hp], apl, vh[0], vh[1]);
                mma16816(o[2 * hp + 1], aph, vh[2], vh[3]);
                mma16816(o[2 * hp + 1], aph, vl[2], vl[3]);
                mma16816(o[2 * hp + 1], apl, vh[2], vh[3]);
            }
        }
    }

    // ---- finalize and write ctx as bf16 hi/lo ----
    const float inv0 = 1.0f / l0;
    const float inv1 = 1.0f / l1;
    #pragma unroll
    for (int nf = 0; nf < 8; nf++) {
        const int col = nf * 8 + tig * 2;
        float2 v0, v1;
        v0.x = o[nf][0] * inv0; v0.y = o[nf][1] * inv0;
        v1.x = o[nf][2] * inv1; v1.y = o[nf][3] * inv1;
        __nv_bfloat162 h0 = __float22bfloat162_rn(v0);
        __nv_bfloat162 h1 = __float22bfloat162_rn(v1);
        float2 r0v, r1v;
        r0v.x = v0.x - __bfloat162float(h0.x);
        r0v.y = v0.y - __bfloat162float(h0.y);
        r1v.x = v1.x - __bfloat162float(h1.x);
        r1v.y = v1.y - __bfloat162float(h1.y);
        __nv_bfloat162 l0b = __float22bfloat162_rn(r0v);
        __nv_bfloat162 l1b = __float22bfloat162_rn(r1v);
        const size_t o0 = base + (size_t)row0 * MHA_D + col;
        const size_t o1 = base + (size_t)row1 * MHA_D + col;
        *(__nv_bfloat162*)(Chi + o0) = h0;
        *(__nv_bfloat162*)(Clo + o0) = l0b;
        *(__nv_bfloat162*)(Chi + o1) = h1;
        *(__nv_bfloat162*)(Clo + o1) = l1b;
    }
}

// ---------------------------------------------------------------------------
extern "C" void kernel_launch(void* const* d_in, const int* in_sizes, int n_in,
                              void* d_out, int out_size)
{
    const float* x  = (const float*)d_in[0];
    const float* Wq = (const float*)d_in[1];
    const float* Wk = (const float*)d_in[2];
    const float* Wv = (const float*)d_in[3];
    const float* Wo = (const float*)d_in[4];
    const float* bo = (const float*)d_in[5];
    float* out = (float*)d_out;

    __nv_bfloat16 *xhi, *xlo;
    __nv_bfloat16 *qhi, *qlo, *khi, *klo, *vhi, *vlo, *chi, *clo;
    __nv_bfloat16 *wqh, *wql, *wkh, *wkl, *wvh, *wvl, *woh, *wol;
    cudaGetSymbolAddress((void**)&xhi, g_xhi);
    cudaGetSymbolAddress((void**)&xlo, g_xlo);
    cudaGetSymbolAddress((void**)&qhi, g_qhi);
    cudaGetSymbolAddress((void**)&qlo, g_qlo);
    cudaGetSymbolAddress((void**)&khi, g_khi);
    cudaGetSymbolAddress((void**)&klo, g_klo);
    cudaGetSymbolAddress((void**)&vhi, g_vhi);
    cudaGetSymbolAddress((void**)&vlo, g_vlo);
    cudaGetSymbolAddress((void**)&chi, g_chi);
    cudaGetSymbolAddress((void**)&clo, g_clo);
    cudaGetSymbolAddress((void**)&wqh, g_wqt_hi);
    cudaGetSymbolAddress((void**)&wql, g_wqt_lo);
    cudaGetSymbolAddress((void**)&wkh, g_wkt_hi);
    cudaGetSymbolAddress((void**)&wkl, g_wkt_lo);
    cudaGetSymbolAddress((void**)&wvh, g_wvt_hi);
    cudaGetSymbolAddress((void**)&wvl, g_wvt_lo);
    cudaGetSymbolAddress((void**)&woh, g_wot_hi);
    cudaGetSymbolAddress((void**)&wol, g_wot_lo);

    cudaFuncSetAttribute(flash_tc_kernel,
                         cudaFuncAttributeMaxDynamicSharedMemorySize, SF_TOTAL);
    cudaFuncSetAttribute(gemm_hmma_kernel<true, false>,
                         cudaFuncAttributeMaxDynamicSharedMemorySize, SM_GEMM_TOTAL);
    cudaFuncSetAttribute(gemm_hmma_kernel<false, true>,
                         cudaFuncAttributeMaxDynamicSharedMemorySize, SM_GEMM_TOTAL);

    // x -> bf16 hi/lo; weights -> transposed bf16 hi/lo
    split_kernel<<<NTOK * MHA_D / 1024, 256>>>(x, xhi, xlo);
    dim3 tgrid(MHA_D / 32, MHA_D / 32), tblk(32, 8);
    transpose_split_kernel<<<tgrid, tblk>>>(Wq, wqh, wql);
    transpose_split_kernel<<<tgrid, tblk>>>(Wk, wkh, wkl);
    transpose_split_kernel<<<tgrid, tblk>>>(Wv, wvh, wvl);
    transpose_split_kernel<<<tgrid, tblk>>>(Wo, woh, wol);

    // QKV projections -> split bf16 outputs (Q pre-scaled by 1/sqrt(HD))
    dim3 ggrid(GM_N / GT_N, GM_M / GT_M);
    gemm_hmma_kernel<true, false><<<ggrid, 256, SM_GEMM_TOTAL>>>(
        xhi, xlo, wqh, wql, nullptr, nullptr, qhi, qlo, 0.125f);
    gemm_hmma_kernel<true, false><<<ggrid, 256, SM_GEMM_TOTAL>>>(
        xhi, xlo, wkh, wkl, nullptr, nullptr, khi, klo, 1.0f);
    gemm_hmma_kernel<true, false><<<ggrid, 256, SM_GEMM_TOTAL>>>(
        xhi, xlo, wvh, wvl, nullptr, nullptr, vhi, vlo, 1.0f);

    // Tensor-core causal flash attention -> split bf16 ctx
    dim3 fa_grid(MHA_S / 64, MHA_B * MHA_H);
    flash_tc_kernel<<<fa_grid, 128, SF_TOTAL>>>(qhi, qlo, khi, klo, vhi, vlo, chi, clo);

    // Output projection with bias (fp32 out)
    gemm_hmma_kernel<false, true><<<ggrid, 256, SM_GEMM_TOTAL>>>(
        chi, clo, woh, wol, bo, out, nullptr, nullptr, 1.0f);
}